// round 9
// baseline (speedup 1.0000x reference)
#include <cuda_runtime.h>
#include <cstdint>

// PhysicsAttention: N=64, C=128, T=256, V=25, O=128
// Round 9: fused warp-per-tile (R8 math), weights via __ldg/L1 (no weight smem),
// 82.9KB smem/CTA -> 2 CTAs/SM; PV accumulator split to cut register peak.

#define NT_TOTAL 16384

__device__ uint32_t g_Bfrag[32768];  // Mhi|Mlo|Vhi|Vlo fragment-ordered images (8192 u32 each)
__device__ float g_u[128];
__device__ float g_bias[25 * 26];

// ---------------- helpers ----------------
__device__ __forceinline__ unsigned short f2bf(float f) {
    unsigned short u;
    asm("cvt.rn.bf16.f32 %0, %1;" : "=h"(u) : "f"(f));
    return u;
}
__device__ __forceinline__ float bf2f(unsigned short u) {
    return __uint_as_float(((uint32_t)u) << 16);
}
__device__ __forceinline__ uint32_t pack_bf(float a, float b) {
    return (uint32_t)f2bf(a) | ((uint32_t)f2bf(b) << 16);
}
__device__ __forceinline__ unsigned long long pk2(float a, float b) {
    unsigned long long r;
    asm("mov.b64 %0, {%1, %2};" : "=l"(r) : "f"(a), "f"(b));
    return r;
}
__device__ __forceinline__ void upk2(unsigned long long x, float& a, float& b) {
    asm("mov.b64 {%0, %1}, %2;" : "=f"(a), "=f"(b) : "l"(x));
}
__device__ __forceinline__ unsigned long long fma2(unsigned long long a,
                                                   unsigned long long b,
                                                   unsigned long long c) {
    unsigned long long d;
    asm("fma.rn.f32x2 %0, %1, %2, %3;" : "=l"(d) : "l"(a), "l"(b), "l"(c));
    return d;
}

#define MMA_BF16(d, a, b0v, b1v)                                                  \
    asm("mma.sync.aligned.m16n8k16.row.col.f32.bf16.bf16.f32 "                    \
        "{%0,%1,%2,%3},{%4,%5,%6,%7},{%8,%9},{%0,%1,%2,%3};"                      \
        : "+f"((d)[0]), "+f"((d)[1]), "+f"((d)[2]), "+f"((d)[3])                  \
        : "r"((a)[0]), "r"((a)[1]), "r"((a)[2]), "r"((a)[3]), "r"(b0v), "r"(b1v))

// X-image smem layout: [row 0..31][kp 0..63] u32 pairs, XOR swizzle (conflict-free
// for row-major writes, A-frag reads, and B-frag reads):
__device__ __forceinline__ int aidx(int row, int kp) {
    return row * 64 + (kp ^ (((row & 15) << 2) | ((row >> 3) & 3)));
}
// Vs fp32 [row 0..31][o 0..127] with XOR swizzle on o (conflict-free frag-stores + lane reads)
__device__ __forceinline__ int vsidx(int row, int o) {
    return row * 128 + (o ^ ((row & 7) << 3));
}

// ---------------- precompute: frag-ordered weight images, u, bias (proven) ----------------
__global__ void precompute_kernel(const float* __restrict__ wq,
                                  const float* __restrict__ bq,
                                  const float* __restrict__ wk,
                                  const float* __restrict__ wv,
                                  const float* __restrict__ bias_emb,
                                  const int* __restrict__ hop) {
    const float inv = 0.088388347648318447f;  // 1/sqrt(128)
    int b = blockIdx.x, k = threadIdx.x;
    if (b < 128) {
        const int n = b;
        float m = 0.f;
#pragma unroll 8
        for (int o = 0; o < 128; o++) m += wq[o * 128 + k] * wk[o * 128 + n];
        m *= inv;
        float wvv = wv[n * 128 + k];
        const int nt = n >> 3, j = n & 7, i = k & 15, ks = k >> 4;
        const int lane = j * 4 + ((i & 7) >> 1);
        const int reg = i >> 3;
        const int half = i & 1;
        const int u32idx = ((nt * 8 + ks) * 32 + lane) * 2 + reg;
        unsigned short* B16 = (unsigned short*)g_Bfrag;
        unsigned short mh = f2bf(m);
        unsigned short vh = f2bf(wvv);
        B16[(0 * 8192 + u32idx) * 2 + half] = mh;
        B16[(1 * 8192 + u32idx) * 2 + half] = f2bf(m - bf2f(mh));
        B16[(2 * 8192 + u32idx) * 2 + half] = vh;
        B16[(3 * 8192 + u32idx) * 2 + half] = f2bf(wvv - bf2f(vh));
    } else if (b == 128) {
        float uu = 0.f;
#pragma unroll 8
        for (int o = 0; o < 128; o++) uu += bq[o] * wk[o * 128 + k];
        g_u[k] = uu * inv;
    } else {
        for (int i = k; i < 625; i += 128) {
            int v = i / 25, w = i - v * 25;
            g_bias[v * 26 + w] = bias_emb[hop[i]];
        }
    }
}

// 3-pass split GEMM: acc[2][16][4] += (Xh+Xl)*(Bh+Bl) (dropping lo*lo).
// B-fragments loaded from GLOBAL (same addrs across all warps -> L1 resident).
__device__ __forceinline__ void gemm3(float acc[2][16][4],
                                      const uint32_t* __restrict__ Xh,
                                      const uint32_t* __restrict__ Xl,
                                      const uint2* __restrict__ Bh,
                                      const uint2* __restrict__ Bl,
                                      int lane, int g, int tc) {
#pragma unroll 1
    for (int pass = 0; pass < 3; pass++) {
        const uint32_t* Ai = (pass == 2) ? Xl : Xh;
        const uint2* Bi = (pass == 1) ? Bl : Bh;
#pragma unroll 1
        for (int ks = 0; ks < 8; ks++) {
            const int kp0 = ks * 8 + tc;
            uint32_t a0[4], a1[4];
            a0[0] = Ai[aidx(g, kp0)];
            a0[1] = Ai[aidx(g + 8, kp0)];
            a0[2] = Ai[aidx(g, kp0 + 4)];
            a0[3] = Ai[aidx(g + 8, kp0 + 4)];
            a1[0] = Ai[aidx(16 + g, kp0)];
            a1[1] = Ai[aidx(24 + g, kp0)];
            a1[2] = Ai[aidx(16 + g, kp0 + 4)];
            a1[3] = Ai[aidx(24 + g, kp0 + 4)];
#pragma unroll
            for (int nt = 0; nt < 16; nt++) {
                const uint2 b = __ldg(&Bi[(nt * 8 + ks) * 32 + lane]);
                MMA_BF16(acc[0][nt], a0, b.x, b.y);
                MMA_BF16(acc[1][nt], a1, b.x, b.y);
            }
        }
    }
}

// ---------------- fused kernel: 4 warps/CTA, 1 tile/warp, 2 CTAs/SM ----------------
// smem per CTA: 4 x (X image 16KB) + 4 x (atp 4352B) = 82944 B
extern __shared__ uint32_t sm[];

__global__ __launch_bounds__(128) void fused_kernel(const float* __restrict__ x,
                                                    const float* __restrict__ bv,
                                                    float* __restrict__ out) {
    const int tid = threadIdx.x;
    const int lane = tid & 31;
    const int w = tid >> 5;
    const int g = lane >> 2, tc = lane & 3;

    uint32_t* Xhi = sm + w * 4096;                 // 2048 u32
    uint32_t* Xlo = Xhi + 2048;                    // 2048 u32
    float* atp = (float*)(sm + 16384 + w * 1088);  // attn^T[w][v], stride 34

    const uint2* Bfr = (const uint2*)g_Bfrag;      // 4 images x 4096 uint2

    const int tile = blockIdx.x * 4 + w;
    const int n = tile >> 8;
    const int t = tile & 255;
    const long xbase = (long)n * 819200 + (long)t * 25;

    // ---- x tile -> hi/lo images (lane = row v; rows >=25 zeroed) ----
    {
        const bool valid = lane < 25;
        const float* xr = x + xbase + lane;
#pragma unroll 4
        for (int kp = 0; kp < 64; kp++) {
            float x0 = valid ? xr[(long)kp * 12800] : 0.f;
            float x1 = valid ? xr[(long)kp * 12800 + 6400] : 0.f;
            unsigned short h0 = f2bf(x0), h1 = f2bf(x1);
            const int si = aidx(lane, kp);
            Xhi[si] = (uint32_t)h0 | ((uint32_t)h1 << 16);
            Xlo[si] = pack_bf(x0 - bf2f(h0), x1 - bf2f(h1));
        }
    }
    __syncwarp();

    // ---- G = X*M (+u)  [rows v x cols c'] ----
    float acc[2][16][4];
#pragma unroll
    for (int m = 0; m < 2; m++)
#pragma unroll
        for (int nt = 0; nt < 16; nt++)
#pragma unroll
            for (int q = 0; q < 4; q++) acc[m][nt][q] = 0.f;
    gemm3(acc, Xhi, Xlo, Bfr, Bfr + 4096, lane, g, tc);

    // ---- +u, split G into A-fragments (in-register: acc layout == A-frag layout) ----
    uint32_t GhA[2][8][4], GlA[2][8][4];
#pragma unroll
    for (int m = 0; m < 2; m++) {
#pragma unroll
        for (int kk = 0; kk < 8; kk++) {
            float2 ua = *(const float2*)(g_u + 16 * kk + 2 * tc);
            float2 ub = *(const float2*)(g_u + 16 * kk + 8 + 2 * tc);
            float v00 = acc[m][2 * kk][0] + ua.x, v01 = acc[m][2 * kk][1] + ua.y;
            float v10 = acc[m][2 * kk][2] + ua.x, v11 = acc[m][2 * kk][3] + ua.y;
            float v20 = acc[m][2 * kk + 1][0] + ub.x, v21 = acc[m][2 * kk + 1][1] + ub.y;
            float v30 = acc[m][2 * kk + 1][2] + ub.x, v31 = acc[m][2 * kk + 1][3] + ub.y;
            unsigned short h00 = f2bf(v00), h01 = f2bf(v01), h10 = f2bf(v10), h11 = f2bf(v11);
            unsigned short h20 = f2bf(v20), h21 = f2bf(v21), h30 = f2bf(v30), h31 = f2bf(v31);
            GhA[m][kk][0] = (uint32_t)h00 | ((uint32_t)h01 << 16);
            GhA[m][kk][1] = (uint32_t)h10 | ((uint32_t)h11 << 16);
            GhA[m][kk][2] = (uint32_t)h20 | ((uint32_t)h21 << 16);
            GhA[m][kk][3] = (uint32_t)h30 | ((uint32_t)h31 << 16);
            GlA[m][kk][0] = pack_bf(v00 - bf2f(h00), v01 - bf2f(h01));
            GlA[m][kk][1] = pack_bf(v10 - bf2f(h10), v11 - bf2f(h11));
            GlA[m][kk][2] = pack_bf(v20 - bf2f(h20), v21 - bf2f(h21));
            GlA[m][kk][3] = pack_bf(v30 - bf2f(h30), v31 - bf2f(h31));
        }
    }

    // ---- S = G * X^T  [rows v x cols w], B-frags read from X image ----
    float S[2][4][4];
#pragma unroll
    for (int m = 0; m < 2; m++)
#pragma unroll
        for (int nt = 0; nt < 4; nt++)
#pragma unroll
            for (int q = 0; q < 4; q++) S[m][nt][q] = 0.f;
#pragma unroll 1
    for (int pass = 0; pass < 3; pass++) {
        const uint32_t(*Aa)[8][4] = (pass == 2) ? GlA : GhA;
        const uint32_t* Bi = (pass == 1) ? Xlo : Xhi;
#pragma unroll 1
        for (int ks = 0; ks < 8; ks++) {
#pragma unroll
            for (int nt = 0; nt < 4; nt++) {
                uint32_t b0 = Bi[aidx(8 * nt + g, 8 * ks + tc)];
                uint32_t b1 = Bi[aidx(8 * nt + g, 8 * ks + tc + 4)];
                MMA_BF16(S[0][nt], Aa[0][ks], b0, b1);
                MMA_BF16(S[1][nt], Aa[1][ks], b0, b1);
            }
        }
    }

    // ---- bias + mask + softmax (rows live in 4-lane groups) ----
#pragma unroll
    for (int m = 0; m < 2; m++) {
        const int v0 = 16 * m + g;
        const int v1c = (v0 + 8 < 25) ? v0 + 8 : 24;  // clamp for bias index only
#pragma unroll
        for (int nt = 0; nt < 4; nt++) {
            const int w0 = 8 * nt + 2 * tc, w1 = w0 + 1;
            if (w0 < 25) {
                S[m][nt][0] += g_bias[v0 * 26 + w0];
                S[m][nt][2] += g_bias[v1c * 26 + w0];
            } else {
                S[m][nt][0] = -1e30f;
                S[m][nt][2] = -1e30f;
            }
            if (w1 < 25) {
                S[m][nt][1] += g_bias[v0 * 26 + w1];
                S[m][nt][3] += g_bias[v1c * 26 + w1];
            } else {
                S[m][nt][1] = -1e30f;
                S[m][nt][3] = -1e30f;
            }
        }
    }
#pragma unroll
    for (int m = 0; m < 2; m++) {
#pragma unroll
        for (int h = 0; h < 2; h++) {
            float mx = -1e30f;
#pragma unroll
            for (int nt = 0; nt < 4; nt++)
                mx = fmaxf(mx, fmaxf(S[m][nt][2 * h], S[m][nt][2 * h + 1]));
            mx = fmaxf(mx, __shfl_xor_sync(0xffffffffu, mx, 1));
            mx = fmaxf(mx, __shfl_xor_sync(0xffffffffu, mx, 2));
            float sum = 0.f;
#pragma unroll
            for (int nt = 0; nt < 4; nt++) {
                float e0 = __expf(S[m][nt][2 * h] - mx);
                float e1 = __expf(S[m][nt][2 * h + 1] - mx);
                S[m][nt][2 * h] = e0;
                S[m][nt][2 * h + 1] = e1;
                sum += e0 + e1;
            }
            sum += __shfl_xor_sync(0xffffffffu, sum, 1);
            sum += __shfl_xor_sync(0xffffffffu, sum, 2);
            float inv = __fdividef(1.f, sum);
#pragma unroll
            for (int nt = 0; nt < 4; nt++) {
                S[m][nt][2 * h] *= inv;
                S[m][nt][2 * h + 1] *= inv;
            }
        }
    }
    // store P transposed: at[w][v], stride 34
#pragma unroll
    for (int m = 0; m < 2; m++)
#pragma unroll
        for (int nt = 0; nt < 4; nt++) {
            const int w0 = 8 * nt + 2 * tc, r = 16 * m + g;
            atp[w0 * 34 + r] = S[m][nt][0];
            atp[(w0 + 1) * 34 + r] = S[m][nt][1];
            atp[w0 * 34 + r + 8] = S[m][nt][2];
            atp[(w0 + 1) * 34 + r + 8] = S[m][nt][3];
        }

    // ---- V = X * wv^T  [rows w x cols o]  (no bv: folded into out via sum(P)=1) ----
#pragma unroll
    for (int m = 0; m < 2; m++)
#pragma unroll
        for (int nt = 0; nt < 16; nt++)
#pragma unroll
            for (int q = 0; q < 4; q++) acc[m][nt][q] = 0.f;
    gemm3(acc, Xhi, Xlo, Bfr + 8192, Bfr + 12288, lane, g, tc);

    __syncwarp();
    // V acc -> Vs fp32 (overwrite X image; warp-private)
    float* Vs = (float*)Xhi;
#pragma unroll
    for (int m = 0; m < 2; m++)
#pragma unroll
        for (int nt = 0; nt < 16; nt++) {
            const int r0 = 16 * m + g, o0 = 8 * nt + 2 * tc;
            *(float2*)&Vs[vsidx(r0, o0)] = make_float2(acc[m][nt][0], acc[m][nt][1]);
            *(float2*)&Vs[vsidx(r0 + 8, o0)] = make_float2(acc[m][nt][2], acc[m][nt][3]);
        }
    __syncwarp();

    // ---- out[v][o] = sum_w P[v][w]*V[w][o] + bv[o]  (fp32 SIMT, split into 2 o-halves
    //      to cut register peak; lane owns 2 o-cols per half) ----
    float outreg[4][26];
#pragma unroll 1
    for (int jh = 0; jh < 2; jh++) {
        unsigned long long accO[2][13];
#pragma unroll
        for (int j = 0; j < 2; j++) {
            float b = __ldg(bv + lane + 32 * (2 * jh + j));
#pragma unroll
            for (int p = 0; p < 13; p++) accO[j][p] = pk2(b, b);
        }
#pragma unroll 1
        for (int wv = 0; wv < 25; wv++) {
            const unsigned long long* ar = (const unsigned long long*)(atp + wv * 34);
            unsigned long long ap[13];
#pragma unroll
            for (int p = 0; p < 13; p++) ap[p] = ar[p];
#pragma unroll
            for (int j = 0; j < 2; j++) {
                float vvf = Vs[vsidx(wv, lane + 32 * (2 * jh + j))];
                unsigned long long vv2 = pk2(vvf, vvf);
#pragma unroll
                for (int p = 0; p < 13; p++) accO[j][p] = fma2(ap[p], vv2, accO[j][p]);
            }
        }
#pragma unroll
        for (int j = 0; j < 2; j++)
#pragma unroll
            for (int p = 0; p < 13; p++)
                upk2(accO[j][p], outreg[2 * jh + j][2 * p], outreg[2 * jh + j][2 * p + 1]);
    }
    __syncwarp();

    // stage outs[o][v] (overwrite Vs region), then coalesced store
    float* outs = (float*)Xhi;
#pragma unroll
    for (int j = 0; j < 4; j++) {
        const int o = lane + 32 * j;
#pragma unroll
        for (int p = 0; p < 13; p++)
            *(float2*)&outs[o * 26 + 2 * p] = make_float2(outreg[j][2 * p], outreg[j][2 * p + 1]);
    }
    __syncwarp();

    const long obase = (long)n * 819200 + (long)t * 25;
#pragma unroll 4
    for (int idx = lane; idx < 3200; idx += 32) {
        const int oo = idx / 25;
        const int v = idx - oo * 25;
        out[obase + (long)oo * 6400 + v] = outs[oo * 26 + v];
    }
}

extern "C" void kernel_launch(void* const* d_in, const int* in_sizes, int n_in,
                              void* d_out, int out_size) {
    (void)in_sizes; (void)n_in; (void)out_size;
    const float* x = (const float*)d_in[0];
    const float* wq = (const float*)d_in[1];
    const float* bq = (const float*)d_in[2];
    const float* wk = (const float*)d_in[3];
    // d_in[4] = bk: softmax-invariant (row-constant), unused
    const float* wv = (const float*)d_in[5];
    const float* bv = (const float*)d_in[6];
    const float* be = (const float*)d_in[7];
    const int* hop = (const int*)d_in[8];

    cudaFuncSetAttribute(fused_kernel, cudaFuncAttributeMaxDynamicSharedMemorySize,
                         82944);

    precompute_kernel<<<130, 128>>>(wq, bq, wk, wv, be, hop);
    fused_kernel<<<NT_TOTAL / 4, 128, 82944>>>(x, bv, (float*)d_out);
}

// round 10
// speedup vs baseline: 1.4132x; 1.4132x over previous
#include <cuda_runtime.h>
#include <cstdint>

// PhysicsAttention: N=64, C=128, T=256, V=25, O=128
// Round 10: warp-pair per tile. Weights in smem (128KB/CTA), 8 warps/CTA, 4 tiles/CTA.
// Each warp owns one m16 half of its tile -> half registers, no spills, 864 MMAs/warp.

#define NT_TOTAL 16384

__device__ uint32_t g_Bfrag[32768];  // Mhi|Mlo|Vhi|Vlo fragment-ordered images (8192 u32 each)
__device__ float g_u[128];
__device__ float g_bias[25 * 26];

// ---------------- helpers ----------------
__device__ __forceinline__ unsigned short f2bf(float f) {
    unsigned short u;
    asm("cvt.rn.bf16.f32 %0, %1;" : "=h"(u) : "f"(f));
    return u;
}
__device__ __forceinline__ float bf2f(unsigned short u) {
    return __uint_as_float(((uint32_t)u) << 16);
}
__device__ __forceinline__ uint32_t pack_bf(float a, float b) {
    return (uint32_t)f2bf(a) | ((uint32_t)f2bf(b) << 16);
}
__device__ __forceinline__ unsigned long long pk2(float a, float b) {
    unsigned long long r;
    asm("mov.b64 %0, {%1, %2};" : "=l"(r) : "f"(a), "f"(b));
    return r;
}
__device__ __forceinline__ void upk2(unsigned long long x, float& a, float& b) {
    asm("mov.b64 {%0, %1}, %2;" : "=f"(a), "=f"(b) : "l"(x));
}
__device__ __forceinline__ unsigned long long fma2(unsigned long long a,
                                                   unsigned long long b,
                                                   unsigned long long c) {
    unsigned long long d;
    asm("fma.rn.f32x2 %0, %1, %2, %3;" : "=l"(d) : "l"(a), "l"(b), "l"(c));
    return d;
}

#define MMA_BF16(d, a, b0v, b1v)                                                  \
    asm("mma.sync.aligned.m16n8k16.row.col.f32.bf16.bf16.f32 "                    \
        "{%0,%1,%2,%3},{%4,%5,%6,%7},{%8,%9},{%0,%1,%2,%3};"                      \
        : "+f"((d)[0]), "+f"((d)[1]), "+f"((d)[2]), "+f"((d)[3])                  \
        : "r"((a)[0]), "r"((a)[1]), "r"((a)[2]), "r"((a)[3]), "r"(b0v), "r"(b1v))

// X-image smem layout: [row 0..31][kp 0..63] u32 pairs, XOR swizzle (conflict-free
// for row-major writes, A-frag reads, and B-frag reads):
__device__ __forceinline__ int aidx(int row, int kp) {
    return row * 64 + (kp ^ (((row & 15) << 2) | ((row >> 3) & 3)));
}
// Vs fp32 [row 0..31][o 0..127] with XOR swizzle on o (conflict-free frag-stores + lane reads)
__device__ __forceinline__ int vsidx(int row, int o) {
    return row * 128 + (o ^ ((row & 7) << 3));
}

// ---------------- precompute: frag-ordered weight images, u, bias (proven) ----------------
__global__ void precompute_kernel(const float* __restrict__ wq,
                                  const float* __restrict__ bq,
                                  const float* __restrict__ wk,
                                  const float* __restrict__ wv,
                                  const float* __restrict__ bias_emb,
                                  const int* __restrict__ hop) {
    const float inv = 0.088388347648318447f;  // 1/sqrt(128)
    int b = blockIdx.x, k = threadIdx.x;
    if (b < 128) {
        const int n = b;
        float m = 0.f;
#pragma unroll 8
        for (int o = 0; o < 128; o++) m += wq[o * 128 + k] * wk[o * 128 + n];
        m *= inv;
        float wvv = wv[n * 128 + k];
        const int nt = n >> 3, j = n & 7, i = k & 15, ks = k >> 4;
        const int lane = j * 4 + ((i & 7) >> 1);
        const int reg = i >> 3;
        const int half = i & 1;
        const int u32idx = ((nt * 8 + ks) * 32 + lane) * 2 + reg;
        unsigned short* B16 = (unsigned short*)g_Bfrag;
        unsigned short mh = f2bf(m);
        unsigned short vh = f2bf(wvv);
        B16[(0 * 8192 + u32idx) * 2 + half] = mh;
        B16[(1 * 8192 + u32idx) * 2 + half] = f2bf(m - bf2f(mh));
        B16[(2 * 8192 + u32idx) * 2 + half] = vh;
        B16[(3 * 8192 + u32idx) * 2 + half] = f2bf(wvv - bf2f(vh));
    } else if (b == 128) {
        float uu = 0.f;
#pragma unroll 8
        for (int o = 0; o < 128; o++) uu += bq[o] * wk[o * 128 + k];
        g_u[k] = uu * inv;
    } else {
        for (int i = k; i < 625; i += 128) {
            int v = i / 25, w = i - v * 25;
            g_bias[v * 26 + w] = bias_emb[hop[i]];
        }
    }
}

// 3-pass split half-GEMM for one m16 tile: acc[16][4] += (Xh+Xl)*(Bh+Bl) (drop lo*lo).
__device__ __forceinline__ void gemm3h(float acc[16][4],
                                       const uint32_t* __restrict__ Xh,
                                       const uint32_t* __restrict__ Xl,
                                       const uint32_t* __restrict__ Bh,
                                       const uint32_t* __restrict__ Bl,
                                       int lane, int g, int tc, int row0) {
#pragma unroll 1
    for (int pass = 0; pass < 3; pass++) {
        const uint32_t* Ai = (pass == 2) ? Xl : Xh;
        const uint32_t* Bi = (pass == 1) ? Bl : Bh;
#pragma unroll 1
        for (int ks = 0; ks < 8; ks++) {
            const int kp0 = ks * 8 + tc;
            uint32_t a[4];
            a[0] = Ai[aidx(row0 + g, kp0)];
            a[1] = Ai[aidx(row0 + 8 + g, kp0)];
            a[2] = Ai[aidx(row0 + g, kp0 + 4)];
            a[3] = Ai[aidx(row0 + 8 + g, kp0 + 4)];
#pragma unroll
            for (int nt = 0; nt < 16; nt++) {
                const uint2 b = ((const uint2*)Bi)[(nt * 8 + ks) * 32 + lane];
                MMA_BF16(acc[nt], a, b.x, b.y);
            }
        }
    }
}

// ---------------- fused kernel: 8 warps/CTA, warp-pair per tile, 4 tiles/CTA ----------------
// smem: weights 131072B + 4 x X image 16384B + 4 x atp 4352B = 214016B
extern __shared__ uint32_t sm[];

__global__ __launch_bounds__(256, 1) void fused_kernel(const float* __restrict__ x,
                                                       const float* __restrict__ bv,
                                                       float* __restrict__ out) {
    const int tid = threadIdx.x;
    const int lane = tid & 31;
    const int w = tid >> 5;
    const int mh = w & 1;    // m-half within the tile
    const int tp = w >> 1;   // tile slot 0..3
    const int g = lane >> 2, tc = lane & 3;

    uint32_t* Bs = sm;                              // 32768 u32 weights
    uint32_t* Xhi = sm + 32768 + tp * 4096;         // 2048 u32
    uint32_t* Xlo = Xhi + 2048;                     // 2048 u32
    float* atp = (float*)(sm + 49152 + tp * 1088);  // attn^T[w][v], stride 34

    const int tile = blockIdx.x * 4 + tp;
    const int n = tile >> 8;
    const int t = tile & 255;
    const long xbase = (long)n * 819200 + (long)t * 25;

    // ---- weights -> smem (all 256 threads) ----
    {
        const uint4* src = (const uint4*)g_Bfrag;
        uint4* dst = (uint4*)Bs;
#pragma unroll 8
        for (int i = 0; i < 32; i++) dst[tid + i * 256] = src[tid + i * 256];
    }
    // ---- x tile -> hi/lo images; warp-pair splits kp range (lane = row v) ----
    {
        const bool valid = lane < 25;
        const float* xr = x + xbase + lane;
#pragma unroll 4
        for (int j = 0; j < 32; j++) {
            const int kp = mh * 32 + j;
            float x0 = valid ? xr[(long)kp * 12800] : 0.f;
            float x1 = valid ? xr[(long)kp * 12800 + 6400] : 0.f;
            unsigned short h0 = f2bf(x0), h1 = f2bf(x1);
            const int si = aidx(lane, kp);
            Xhi[si] = (uint32_t)h0 | ((uint32_t)h1 << 16);
            Xlo[si] = pack_bf(x0 - bf2f(h0), x1 - bf2f(h1));
        }
    }
    __syncthreads();

    const int row0 = 16 * mh;

    // ---- G = X*M (+u) for this warp's m16 half ----
    float acc[16][4];
#pragma unroll
    for (int nt = 0; nt < 16; nt++)
#pragma unroll
        for (int q = 0; q < 4; q++) acc[nt][q] = 0.f;
    gemm3h(acc, Xhi, Xlo, Bs, Bs + 8192, lane, g, tc, row0);

    // ---- +u, split G into A-fragments (acc layout == A-frag layout) ----
    uint32_t GhA[8][4], GlA[8][4];
#pragma unroll
    for (int kk = 0; kk < 8; kk++) {
        float2 ua = *(const float2*)(g_u + 16 * kk + 2 * tc);
        float2 ub = *(const float2*)(g_u + 16 * kk + 8 + 2 * tc);
        float v00 = acc[2 * kk][0] + ua.x, v01 = acc[2 * kk][1] + ua.y;
        float v10 = acc[2 * kk][2] + ua.x, v11 = acc[2 * kk][3] + ua.y;
        float v20 = acc[2 * kk + 1][0] + ub.x, v21 = acc[2 * kk + 1][1] + ub.y;
        float v30 = acc[2 * kk + 1][2] + ub.x, v31 = acc[2 * kk + 1][3] + ub.y;
        unsigned short h00 = f2bf(v00), h01 = f2bf(v01), h10 = f2bf(v10), h11 = f2bf(v11);
        unsigned short h20 = f2bf(v20), h21 = f2bf(v21), h30 = f2bf(v30), h31 = f2bf(v31);
        GhA[kk][0] = (uint32_t)h00 | ((uint32_t)h01 << 16);
        GhA[kk][1] = (uint32_t)h10 | ((uint32_t)h11 << 16);
        GhA[kk][2] = (uint32_t)h20 | ((uint32_t)h21 << 16);
        GhA[kk][3] = (uint32_t)h30 | ((uint32_t)h31 << 16);
        GlA[kk][0] = pack_bf(v00 - bf2f(h00), v01 - bf2f(h01));
        GlA[kk][1] = pack_bf(v10 - bf2f(h10), v11 - bf2f(h11));
        GlA[kk][2] = pack_bf(v20 - bf2f(h20), v21 - bf2f(h21));
        GlA[kk][3] = pack_bf(v30 - bf2f(h30), v31 - bf2f(h31));
    }

    // ---- S = G * X^T for this warp's 16 rows ----
    float S[4][4];
#pragma unroll
    for (int nt = 0; nt < 4; nt++)
#pragma unroll
        for (int q = 0; q < 4; q++) S[nt][q] = 0.f;
#pragma unroll 1
    for (int pass = 0; pass < 3; pass++) {
        const uint32_t(*Aa)[4] = (pass == 2) ? GlA : GhA;
        const uint32_t* Bi = (pass == 1) ? Xlo : Xhi;
#pragma unroll 1
        for (int ks = 0; ks < 8; ks++) {
#pragma unroll
            for (int nt = 0; nt < 4; nt++) {
                uint32_t b0 = Bi[aidx(8 * nt + g, 8 * ks + tc)];
                uint32_t b1 = Bi[aidx(8 * nt + g, 8 * ks + tc + 4)];
                MMA_BF16(S[nt], Aa[ks], b0, b1);
            }
        }
    }

    // ---- bias + mask + softmax (rows live in 4-lane groups) ----
    {
        const int v0 = row0 + g;
        const int v1c = (v0 + 8 < 25) ? v0 + 8 : 24;  // index clamp only
#pragma unroll
        for (int nt = 0; nt < 4; nt++) {
            const int w0 = 8 * nt + 2 * tc, w1 = w0 + 1;
            if (w0 < 25) {
                S[nt][0] += g_bias[v0 * 26 + w0];
                S[nt][2] += g_bias[v1c * 26 + w0];
            } else {
                S[nt][0] = -1e30f;
                S[nt][2] = -1e30f;
            }
            if (w1 < 25) {
                S[nt][1] += g_bias[v0 * 26 + w1];
                S[nt][3] += g_bias[v1c * 26 + w1];
            } else {
                S[nt][1] = -1e30f;
                S[nt][3] = -1e30f;
            }
        }
    }
#pragma unroll
    for (int h = 0; h < 2; h++) {
        float mx = -1e30f;
#pragma unroll
        for (int nt = 0; nt < 4; nt++)
            mx = fmaxf(mx, fmaxf(S[nt][2 * h], S[nt][2 * h + 1]));
        mx = fmaxf(mx, __shfl_xor_sync(0xffffffffu, mx, 1));
        mx = fmaxf(mx, __shfl_xor_sync(0xffffffffu, mx, 2));
        float sum = 0.f;
#pragma unroll
        for (int nt = 0; nt < 4; nt++) {
            float e0 = __expf(S[nt][2 * h] - mx);
            float e1 = __expf(S[nt][2 * h + 1] - mx);
            S[nt][2 * h] = e0;
            S[nt][2 * h + 1] = e1;
            sum += e0 + e1;
        }
        sum += __shfl_xor_sync(0xffffffffu, sum, 1);
        sum += __shfl_xor_sync(0xffffffffu, sum, 2);
        float inv = __fdividef(1.f, sum);
#pragma unroll
        for (int nt = 0; nt < 4; nt++) {
            S[nt][2 * h] *= inv;
            S[nt][2 * h + 1] *= inv;
        }
    }
    // store P transposed: atp[w][v], stride 34 (warp writes its 16 v-columns)
#pragma unroll
    for (int nt = 0; nt < 4; nt++) {
        const int w0 = 8 * nt + 2 * tc, r = row0 + g;
        atp[w0 * 34 + r] = S[nt][0];
        atp[(w0 + 1) * 34 + r] = S[nt][1];
        atp[w0 * 34 + r + 8] = S[nt][2];
        atp[(w0 + 1) * 34 + r + 8] = S[nt][3];
    }

    // ---- V = X * wv^T for this warp's 16 rows (bv folded into PV via sum(P)=1) ----
#pragma unroll
    for (int nt = 0; nt < 16; nt++)
#pragma unroll
        for (int q = 0; q < 4; q++) acc[nt][q] = 0.f;
    gemm3h(acc, Xhi, Xlo, Bs + 16384, Bs + 24576, lane, g, tc, row0);

    __syncthreads();  // both warps of each pair done reading X images
    // V acc -> Vs fp32 (overwrite X image; 32 rows x 128 shared by the pair)
    float* Vs = (float*)Xhi;
#pragma unroll
    for (int nt = 0; nt < 16; nt++) {
        const int r0 = row0 + g, o0 = 8 * nt + 2 * tc;
        *(float2*)&Vs[vsidx(r0, o0)] = make_float2(acc[nt][0], acc[nt][1]);
        *(float2*)&Vs[vsidx(r0 + 8, o0)] = make_float2(acc[nt][2], acc[nt][3]);
    }
    __syncthreads();  // Vs + atp complete for the pair

    // ---- out[v][o] = sum_w P[v][w]*V[w][o] + bv[o]; warp owns o-half 64*mh..64*mh+63 ----
    float outreg[2][26];
    {
        unsigned long long accO[2][13];
#pragma unroll
        for (int j = 0; j < 2; j++) {
            float b = __ldg(bv + lane + 32 * j + 64 * mh);
#pragma unroll
            for (int p = 0; p < 13; p++) accO[j][p] = pk2(b, b);
        }
#pragma unroll 1
        for (int wv = 0; wv < 25; wv++) {
            const unsigned long long* ar = (const unsigned long long*)(atp + wv * 34);
            unsigned long long ap[13];
#pragma unroll
            for (int p = 0; p < 13; p++) ap[p] = ar[p];
#pragma unroll
            for (int j = 0; j < 2; j++) {
                float vvf = Vs[vsidx(wv, lane + 32 * j + 64 * mh)];
                unsigned long long vv2 = pk2(vvf, vvf);
#pragma unroll
                for (int p = 0; p < 13; p++) accO[j][p] = fma2(ap[p], vv2, accO[j][p]);
            }
        }
#pragma unroll
        for (int j = 0; j < 2; j++)
#pragma unroll
            for (int p = 0; p < 13; p++)
                upk2(accO[j][p], outreg[j][2 * p], outreg[j][2 * p + 1]);
    }
    __syncthreads();  // all PV reads of Vs done before overwrite

    // stage outs[o][v] (overwrite Vs region), then coalesced store by the pair
    float* outs = (float*)Xhi;
#pragma unroll
    for (int j = 0; j < 2; j++) {
        const int o = lane + 32 * j + 64 * mh;
#pragma unroll
        for (int p = 0; p < 13; p++)
            *(float2*)&outs[o * 26 + 2 * p] = make_float2(outreg[j][2 * p], outreg[j][2 * p + 1]);
    }
    __syncthreads();

    const long obase = (long)n * 819200 + (long)t * 25;
#pragma unroll 4
    for (int idx = lane + 32 * mh; idx < 3200; idx += 64) {
        const int oo = idx / 25;
        const int v = idx - oo * 25;
        out[obase + (long)oo * 6400 + v] = outs[oo * 26 + v];
    }
}

extern "C" void kernel_launch(void* const* d_in, const int* in_sizes, int n_in,
                              void* d_out, int out_size) {
    (void)in_sizes; (void)n_in; (void)out_size;
    const float* x = (const float*)d_in[0];
    const float* wq = (const float*)d_in[1];
    const float* bq = (const float*)d_in[2];
    const float* wk = (const float*)d_in[3];
    // d_in[4] = bk: softmax-invariant (row-constant), unused
    const float* wv = (const float*)d_in[5];
    const float* bv = (const float*)d_in[6];
    const float* be = (const float*)d_in[7];
    const int* hop = (const int*)d_in[8];

    cudaFuncSetAttribute(fused_kernel, cudaFuncAttributeMaxDynamicSharedMemorySize,
                         214016);

    precompute_kernel<<<130, 128>>>(wq, bq, wk, wv, be, hop);
    fused_kernel<<<NT_TOTAL / 4, 256, 214016>>>(x, bv, (float*)d_out);
}

// round 11
// speedup vs baseline: 2.0574x; 1.4559x over previous
#include <cuda_runtime.h>
#include <cstdint>

// PhysicsAttention: N=64, C=128, T=256, V=25, O=128
// Round 11: fp16 pipeline. M-path 3-pass fp16 hi/lo split; V-path single-pass fp16.
// Weights in L1-resident global (96KB), smem = X images only (64KB/CTA) -> 2 CTAs/SM,
// 16 warps/SM. Warp-pair per tile (R10 structure), <=128 regs.

#define NT_TOTAL 16384

__device__ uint32_t g_Wf[24576];  // frag-ordered fp16 images: Mhi | Mlo | Vf16 (8192 u32 each)
__device__ float g_u[128];
__device__ float g_bias[25 * 26];

// ---------------- helpers ----------------
__device__ __forceinline__ unsigned short f2h(float f) {
    unsigned short u;
    asm("cvt.rn.f16.f32 %0, %1;" : "=h"(u) : "f"(f));
    return u;
}
__device__ __forceinline__ float h2f(unsigned short u) {
    float f;
    asm("cvt.f32.f16 %0, %1;" : "=f"(f) : "h"(u));
    return f;
}
__device__ __forceinline__ uint32_t packh(float a, float b) {
    return (uint32_t)f2h(a) | ((uint32_t)f2h(b) << 16);
}
__device__ __forceinline__ unsigned long long pk2(float a, float b) {
    unsigned long long r;
    asm("mov.b64 %0, {%1, %2};" : "=l"(r) : "f"(a), "f"(b));
    return r;
}
__device__ __forceinline__ void upk2(unsigned long long x, float& a, float& b) {
    asm("mov.b64 {%0, %1}, %2;" : "=f"(a), "=f"(b) : "l"(x));
}
__device__ __forceinline__ unsigned long long fma2(unsigned long long a,
                                                   unsigned long long b,
                                                   unsigned long long c) {
    unsigned long long d;
    asm("fma.rn.f32x2 %0, %1, %2, %3;" : "=l"(d) : "l"(a), "l"(b), "l"(c));
    return d;
}

#define MMA_F16(d, a, b0v, b1v)                                                   \
    asm("mma.sync.aligned.m16n8k16.row.col.f32.f16.f16.f32 "                      \
        "{%0,%1,%2,%3},{%4,%5,%6,%7},{%8,%9},{%0,%1,%2,%3};"                      \
        : "+f"((d)[0]), "+f"((d)[1]), "+f"((d)[2]), "+f"((d)[3])                  \
        : "r"((a)[0]), "r"((a)[1]), "r"((a)[2]), "r"((a)[3]), "r"(b0v), "r"(b1v))

// X-image smem layout: [row 0..31][kp 0..63] u32 pairs, XOR swizzle (proven):
__device__ __forceinline__ int aidx(int row, int kp) {
    return row * 64 + (kp ^ (((row & 15) << 2) | ((row >> 3) & 3)));
}
// Vs fp16 [32][128]: elem idx with o XOR (conflict-free frag stores + PV reads)
__device__ __forceinline__ int vsidx2(int row, int o) {
    return row * 128 + (o ^ ((row & 7) << 3));
}

// ---------------- precompute: frag-ordered fp16 weight images, u, bias ----------------
__global__ void precompute_kernel(const float* __restrict__ wq,
                                  const float* __restrict__ bq,
                                  const float* __restrict__ wk,
                                  const float* __restrict__ wv,
                                  const float* __restrict__ bias_emb,
                                  const int* __restrict__ hop) {
    const float inv = 0.088388347648318447f;  // 1/sqrt(128)
    int b = blockIdx.x, k = threadIdx.x;
    if (b < 128) {
        const int n = b;
        float m = 0.f;
#pragma unroll 8
        for (int o = 0; o < 128; o++) m += wq[o * 128 + k] * wk[o * 128 + n];
        m *= inv;
        float wvv = wv[n * 128 + k];
        // fragment position for m16n8k16 B (col) operand
        const int nt = n >> 3, j = n & 7, i = k & 15, ks = k >> 4;
        const int lane = j * 4 + ((i & 7) >> 1);
        const int reg = i >> 3;
        const int half = i & 1;
        const int u32idx = ((nt * 8 + ks) * 32 + lane) * 2 + reg;
        unsigned short* B16 = (unsigned short*)g_Wf;
        unsigned short mh = f2h(m);
        B16[(0 * 8192 + u32idx) * 2 + half] = mh;                  // Mhi
        B16[(1 * 8192 + u32idx) * 2 + half] = f2h(m - h2f(mh));    // Mlo
        B16[(2 * 8192 + u32idx) * 2 + half] = f2h(wvv);            // Vf16
    } else if (b == 128) {
        float uu = 0.f;
#pragma unroll 8
        for (int o = 0; o < 128; o++) uu += bq[o] * wk[o * 128 + k];
        g_u[k] = uu * inv;
    } else {
        for (int i = k; i < 625; i += 128) {
            int v = i / 25, w = i - v * 25;
            g_bias[v * 26 + w] = bias_emb[hop[i]];
        }
    }
}

// ---------------- fused kernel: 8 warps/CTA, warp-pair per tile, 4 tiles/CTA ----------------
// smem: 4 x (X hi/lo image 16KB) = 65536 B -> 2 CTAs/SM
extern __shared__ uint32_t sm[];

__global__ __launch_bounds__(256, 2) void fused_kernel(const float* __restrict__ x,
                                                       const float* __restrict__ bv,
                                                       float* __restrict__ out) {
    const int tid = threadIdx.x;
    const int lane = tid & 31;
    const int w = tid >> 5;
    const int mh = w & 1;   // m-half within the tile
    const int tp = w >> 1;  // tile slot 0..3
    const int g = lane >> 2, tc = lane & 3;

    uint32_t* Xhi = sm + tp * 4096;  // 2048 u32
    uint32_t* Xlo = Xhi + 2048;      // 2048 u32

    const uint2* WfM = (const uint2*)g_Wf;         // hi @0, lo @+4096 (uint2 units)
    const uint2* WfV = (const uint2*)g_Wf + 8192;  // Vf16

    const int tile = blockIdx.x * 4 + tp;
    const int n = tile >> 8;
    const int t = tile & 255;
    const long xbase = (long)n * 819200 + (long)t * 25;

    // ---- x tile -> fp16 hi/lo images; pair splits kp range (lane = row v) ----
    {
        const bool valid = lane < 25;
        const float* xr = x + xbase + lane;
#pragma unroll 4
        for (int j = 0; j < 32; j++) {
            const int kp = mh * 32 + j;
            float x0 = valid ? __ldcs(xr + (long)kp * 12800) : 0.f;
            float x1 = valid ? __ldcs(xr + (long)kp * 12800 + 6400) : 0.f;
            unsigned short h0 = f2h(x0), h1 = f2h(x1);
            const int si = aidx(lane, kp);
            Xhi[si] = (uint32_t)h0 | ((uint32_t)h1 << 16);
            Xlo[si] = packh(x0 - h2f(h0), x1 - h2f(h1));
        }
    }
    __syncthreads();

    const int row0 = 16 * mh;

    // ---- G = X*M (+u), 3-pass fp16 split, n-split into 2 halves (acc 32 regs) ----
    uint32_t GhA[8][4], GlA[8][4];
#pragma unroll 1
    for (int hh = 0; hh < 2; hh++) {
        float acc[8][4];
#pragma unroll
        for (int nt = 0; nt < 8; nt++)
#pragma unroll
            for (int q = 0; q < 4; q++) acc[nt][q] = 0.f;
#pragma unroll 1
        for (int pass = 0; pass < 3; pass++) {
            const uint32_t* Ai = (pass == 2) ? Xlo : Xhi;
            const uint2* Bi = WfM + ((pass == 1) ? 4096 : 0);
#pragma unroll 1
            for (int ks = 0; ks < 8; ks++) {
                const int kp0 = ks * 8 + tc;
                uint32_t a[4];
                a[0] = Ai[aidx(row0 + g, kp0)];
                a[1] = Ai[aidx(row0 + 8 + g, kp0)];
                a[2] = Ai[aidx(row0 + g, kp0 + 4)];
                a[3] = Ai[aidx(row0 + 8 + g, kp0 + 4)];
#pragma unroll
                for (int nt = 0; nt < 8; nt++) {
                    const uint2 b = __ldg(&Bi[(((hh * 8 + nt) * 8) + ks) * 32 + lane]);
                    MMA_F16(acc[nt], a, b.x, b.y);
                }
            }
        }
        // +u, convert this n-half into A-fragments (acc layout == A-frag layout)
#pragma unroll
        for (int kk2 = 0; kk2 < 4; kk2++) {
            const int kk = hh * 4 + kk2;
            float2 ua = *(const float2*)(g_u + 16 * kk + 2 * tc);
            float2 ub = *(const float2*)(g_u + 16 * kk + 8 + 2 * tc);
            float v00 = acc[2 * kk2][0] + ua.x, v01 = acc[2 * kk2][1] + ua.y;
            float v10 = acc[2 * kk2][2] + ua.x, v11 = acc[2 * kk2][3] + ua.y;
            float v20 = acc[2 * kk2 + 1][0] + ub.x, v21 = acc[2 * kk2 + 1][1] + ub.y;
            float v30 = acc[2 * kk2 + 1][2] + ub.x, v31 = acc[2 * kk2 + 1][3] + ub.y;
            unsigned short h00 = f2h(v00), h01 = f2h(v01), h10 = f2h(v10), h11 = f2h(v11);
            unsigned short h20 = f2h(v20), h21 = f2h(v21), h30 = f2h(v30), h31 = f2h(v31);
            GhA[kk][0] = (uint32_t)h00 | ((uint32_t)h01 << 16);
            GhA[kk][1] = (uint32_t)h10 | ((uint32_t)h11 << 16);
            GhA[kk][2] = (uint32_t)h20 | ((uint32_t)h21 << 16);
            GhA[kk][3] = (uint32_t)h30 | ((uint32_t)h31 << 16);
            GlA[kk][0] = packh(v00 - h2f(h00), v01 - h2f(h01));
            GlA[kk][1] = packh(v10 - h2f(h10), v11 - h2f(h11));
            GlA[kk][2] = packh(v20 - h2f(h20), v21 - h2f(h21));
            GlA[kk][3] = packh(v30 - h2f(h30), v31 - h2f(h31));
        }
    }

    // ---- S = G * X^T (3-pass), B-frags from X images ----
    float S[4][4];
#pragma unroll
    for (int nt = 0; nt < 4; nt++)
#pragma unroll
        for (int q = 0; q < 4; q++) S[nt][q] = 0.f;
#pragma unroll 1
    for (int pass = 0; pass < 3; pass++) {
        const uint32_t(*Aa)[4] = (pass == 2) ? GlA : GhA;
        const uint32_t* Bi = (pass == 1) ? Xlo : Xhi;
#pragma unroll 1
        for (int ks = 0; ks < 8; ks++) {
#pragma unroll
            for (int nt = 0; nt < 4; nt++) {
                uint32_t b0 = Bi[aidx(8 * nt + g, 8 * ks + tc)];
                uint32_t b1 = Bi[aidx(8 * nt + g, 8 * ks + tc + 4)];
                MMA_F16(S[nt], Aa[ks], b0, b1);
            }
        }
    }

    // ---- bias + mask + softmax (rows live in 4-lane groups) ----
    {
        const int v0 = row0 + g;
        const int v1c = (v0 + 8 < 25) ? v0 + 8 : 24;  // index clamp only
#pragma unroll
        for (int nt = 0; nt < 4; nt++) {
            const int w0 = 8 * nt + 2 * tc, w1 = w0 + 1;
            if (w0 < 25) {
                S[nt][0] += g_bias[v0 * 26 + w0];
                S[nt][2] += g_bias[v1c * 26 + w0];
            } else {
                S[nt][0] = -1e30f;
                S[nt][2] = -1e30f;
            }
            if (w1 < 25) {
                S[nt][1] += g_bias[v0 * 26 + w1];
                S[nt][3] += g_bias[v1c * 26 + w1];
            } else {
                S[nt][1] = -1e30f;
                S[nt][3] = -1e30f;
            }
        }
    }
#pragma unroll
    for (int h = 0; h < 2; h++) {
        float mx = -1e30f;
#pragma unroll
        for (int nt = 0; nt < 4; nt++)
            mx = fmaxf(mx, fmaxf(S[nt][2 * h], S[nt][2 * h + 1]));
        mx = fmaxf(mx, __shfl_xor_sync(0xffffffffu, mx, 1));
        mx = fmaxf(mx, __shfl_xor_sync(0xffffffffu, mx, 2));
        float sum = 0.f;
#pragma unroll
        for (int nt = 0; nt < 4; nt++) {
            float e0 = __expf(S[nt][2 * h] - mx);
            float e1 = __expf(S[nt][2 * h + 1] - mx);
            S[nt][2 * h] = e0;
            S[nt][2 * h + 1] = e1;
            sum += e0 + e1;
        }
        sum += __shfl_xor_sync(0xffffffffu, sum, 1);
        sum += __shfl_xor_sync(0xffffffffu, sum, 2);
        float inv = __fdividef(1.f, sum);
#pragma unroll
        for (int nt = 0; nt < 4; nt++) {
            S[nt][2 * h] *= inv;
            S[nt][2 * h + 1] *= inv;
        }
    }

    // ---- V = X * wv^T, SINGLE-PASS fp16 (A = Xhi only, B = Vf16 via L1) ----
    float accV[16][4];
#pragma unroll
    for (int nt = 0; nt < 16; nt++)
#pragma unroll
        for (int q = 0; q < 4; q++) accV[nt][q] = 0.f;
#pragma unroll 1
    for (int ks = 0; ks < 8; ks++) {
        const int kp0 = ks * 8 + tc;
        uint32_t a[4];
        a[0] = Xhi[aidx(row0 + g, kp0)];
        a[1] = Xhi[aidx(row0 + 8 + g, kp0)];
        a[2] = Xhi[aidx(row0 + g, kp0 + 4)];
        a[3] = Xhi[aidx(row0 + 8 + g, kp0 + 4)];
#pragma unroll
        for (int nt = 0; nt < 16; nt++) {
            const uint2 b = __ldg(&WfV[(nt * 8 + ks) * 32 + lane]);
            MMA_F16(accV[nt], a, b.x, b.y);
        }
    }
    __syncthreads();  // all warps done reading X images

    // ---- overlay: Vs fp16 -> Xhi region; atp (P^T) -> Xlo region ----
    unsigned short* Vs = (unsigned short*)Xhi;
#pragma unroll
    for (int nt = 0; nt < 16; nt++) {
        const int r0 = row0 + g, o0 = 8 * nt + 2 * tc;
        *(uint32_t*)(Vs + vsidx2(r0, o0)) = packh(accV[nt][0], accV[nt][1]);
        *(uint32_t*)(Vs + vsidx2(r0 + 8, o0)) = packh(accV[nt][2], accV[nt][3]);
    }
    float* atp = (float*)Xlo;  // [w][v] stride 34, 4.3KB
#pragma unroll
    for (int nt = 0; nt < 4; nt++) {
        const int w0 = 8 * nt + 2 * tc, r = row0 + g;
        atp[w0 * 34 + r] = S[nt][0];
        atp[(w0 + 1) * 34 + r] = S[nt][1];
        atp[w0 * 34 + r + 8] = S[nt][2];
        atp[(w0 + 1) * 34 + r + 8] = S[nt][3];
    }
    __syncthreads();

    // ---- out[v][o] = sum_w P[v][w]*V[w][o] + bv[o]; warp owns o-half 64*mh.. ----
    float outreg[2][26];
    {
        unsigned long long accO[2][13];
#pragma unroll
        for (int j = 0; j < 2; j++) {
            float b = __ldg(bv + lane + 32 * j + 64 * mh);
#pragma unroll
            for (int p = 0; p < 13; p++) accO[j][p] = pk2(b, b);
        }
#pragma unroll 1
        for (int wv = 0; wv < 25; wv++) {
            const unsigned long long* ar = (const unsigned long long*)(atp + wv * 34);
            unsigned long long ap[13];
#pragma unroll
            for (int p = 0; p < 13; p++) ap[p] = ar[p];
#pragma unroll
            for (int j = 0; j < 2; j++) {
                float vvf = h2f(Vs[vsidx2(wv, lane + 32 * j + 64 * mh)]);
                unsigned long long vv2 = pk2(vvf, vvf);
#pragma unroll
                for (int p = 0; p < 13; p++) accO[j][p] = fma2(ap[p], vv2, accO[j][p]);
            }
        }
#pragma unroll
        for (int j = 0; j < 2; j++)
#pragma unroll
            for (int p = 0; p < 13; p++)
                upk2(accO[j][p], outreg[j][2 * p], outreg[j][2 * p + 1]);
    }
    __syncthreads();  // PV reads done before overwrite

    // stage outs[o][v] over the tile's 16KB region, then coalesced store by the pair
    float* outs = (float*)Xhi;  // 3200 floats = 12.8KB
#pragma unroll
    for (int j = 0; j < 2; j++) {
        const int o = lane + 32 * j + 64 * mh;
#pragma unroll
        for (int p = 0; p < 13; p++)
            *(float2*)&outs[o * 26 + 2 * p] = make_float2(outreg[j][2 * p], outreg[j][2 * p + 1]);
    }
    __syncthreads();

    const long obase = (long)n * 819200 + (long)t * 25;
#pragma unroll 4
    for (int idx = lane + 32 * mh; idx < 3200; idx += 64) {
        const int oo = idx / 25;
        const int v = idx - oo * 25;
        __stcs(&out[obase + (long)oo * 6400 + v], outs[oo * 26 + v]);
    }
}

extern "C" void kernel_launch(void* const* d_in, const int* in_sizes, int n_in,
                              void* d_out, int out_size) {
    (void)in_sizes; (void)n_in; (void)out_size;
    const float* x = (const float*)d_in[0];
    const float* wq = (const float*)d_in[1];
    const float* bq = (const float*)d_in[2];
    const float* wk = (const float*)d_in[3];
    // d_in[4] = bk: softmax-invariant (row-constant), unused
    const float* wv = (const float*)d_in[5];
    const float* bv = (const float*)d_in[6];
    const float* be = (const float*)d_in[7];
    const int* hop = (const int*)d_in[8];

    cudaFuncSetAttribute(fused_kernel, cudaFuncAttributeMaxDynamicSharedMemorySize,
                         65536);

    precompute_kernel<<<130, 128>>>(wq, bq, wk, wv, be, hop);
    fused_kernel<<<NT_TOTAL / 4, 256, 65536>>>(x, bv, (float*)d_out);
}

// round 12
// speedup vs baseline: 2.2379x; 1.0877x over previous
#include <cuda_runtime.h>
#include <cstdint>

// PhysicsAttention: N=64, C=128, T=256, V=25, O=128
// Round 12: R11 + PV moved onto tensor pipe (P-as-A-frags direct from softmax regs,
// V^T fp16 in stride-20 smem). atp and SIMT PV removed. 2 CTAs/SM, warp-pair/tile.

#define NT_TOTAL 16384

__device__ uint32_t g_Wf[24576];  // frag-ordered fp16 images: Mhi | Mlo | Vf16 (8192 u32 each)
__device__ float g_u[128];
__device__ float g_bias[25 * 26];

// ---------------- helpers ----------------
__device__ __forceinline__ unsigned short f2h(float f) {
    unsigned short u;
    asm("cvt.rn.f16.f32 %0, %1;" : "=h"(u) : "f"(f));
    return u;
}
__device__ __forceinline__ float h2f(unsigned short u) {
    float f;
    asm("cvt.f32.f16 %0, %1;" : "=f"(f) : "h"(u));
    return f;
}
__device__ __forceinline__ uint32_t packh(float a, float b) {
    return (uint32_t)f2h(a) | ((uint32_t)f2h(b) << 16);
}

#define MMA_F16(d, a, b0v, b1v)                                                   \
    asm("mma.sync.aligned.m16n8k16.row.col.f32.f16.f16.f32 "                      \
        "{%0,%1,%2,%3},{%4,%5,%6,%7},{%8,%9},{%0,%1,%2,%3};"                      \
        : "+f"((d)[0]), "+f"((d)[1]), "+f"((d)[2]), "+f"((d)[3])                  \
        : "r"((a)[0]), "r"((a)[1]), "r"((a)[2]), "r"((a)[3]), "r"(b0v), "r"(b1v))

// X-image smem layout: [row 0..31][kp 0..63] u32 pairs, XOR swizzle (proven):
__device__ __forceinline__ int aidx(int row, int kp) {
    return row * 64 + (kp ^ (((row & 15) << 2) | ((row >> 3) & 3)));
}

// ---------------- precompute: frag-ordered fp16 weight images, u, bias ----------------
__global__ void precompute_kernel(const float* __restrict__ wq,
                                  const float* __restrict__ bq,
                                  const float* __restrict__ wk,
                                  const float* __restrict__ wv,
                                  const float* __restrict__ bias_emb,
                                  const int* __restrict__ hop) {
    const float inv = 0.088388347648318447f;  // 1/sqrt(128)
    int b = blockIdx.x, k = threadIdx.x;
    if (b < 128) {
        const int n = b;
        float m = 0.f;
#pragma unroll 8
        for (int o = 0; o < 128; o++) m += wq[o * 128 + k] * wk[o * 128 + n];
        m *= inv;
        float wvv = wv[n * 128 + k];
        // fragment position for m16n8k16 B (col) operand
        const int nt = n >> 3, j = n & 7, i = k & 15, ks = k >> 4;
        const int lane = j * 4 + ((i & 7) >> 1);
        const int reg = i >> 3;
        const int half = i & 1;
        const int u32idx = ((nt * 8 + ks) * 32 + lane) * 2 + reg;
        unsigned short* B16 = (unsigned short*)g_Wf;
        unsigned short mh = f2h(m);
        B16[(0 * 8192 + u32idx) * 2 + half] = mh;                  // Mhi
        B16[(1 * 8192 + u32idx) * 2 + half] = f2h(m - h2f(mh));    // Mlo
        B16[(2 * 8192 + u32idx) * 2 + half] = f2h(wvv);            // Vf16
    } else if (b == 128) {
        float uu = 0.f;
#pragma unroll 8
        for (int o = 0; o < 128; o++) uu += bq[o] * wk[o * 128 + k];
        g_u[k] = uu * inv;
    } else {
        for (int i = k; i < 625; i += 128) {
            int v = i / 25, w = i - v * 25;
            g_bias[v * 26 + w] = bias_emb[hop[i]];
        }
    }
}

// ---------------- fused kernel: 8 warps/CTA, warp-pair per tile, 4 tiles/CTA ----------------
// smem: 4 x (X hi/lo image 16KB) = 65536 B -> 2 CTAs/SM
extern __shared__ uint32_t sm[];

__global__ __launch_bounds__(256, 2) void fused_kernel(const float* __restrict__ x,
                                                       const float* __restrict__ bv,
                                                       float* __restrict__ out) {
    const int tid = threadIdx.x;
    const int lane = tid & 31;
    const int w = tid >> 5;
    const int mh = w & 1;   // m-half within the tile
    const int tp = w >> 1;  // tile slot 0..3
    const int g = lane >> 2, tc = lane & 3;

    uint32_t* Xhi = sm + tp * 4096;  // 2048 u32
    uint32_t* Xlo = Xhi + 2048;      // 2048 u32

    const uint2* WfM = (const uint2*)g_Wf;         // hi @0, lo @+4096 (uint2 units)
    const uint2* WfV = (const uint2*)g_Wf + 8192;  // Vf16

    const int tile = blockIdx.x * 4 + tp;
    const int n = tile >> 8;
    const int t = tile & 255;
    const long xbase = (long)n * 819200 + (long)t * 25;

    // ---- x tile -> fp16 hi/lo images; pair splits kp range (lane = row v) ----
    {
        const bool valid = lane < 25;
        const float* xr = x + xbase + lane;
#pragma unroll 4
        for (int j = 0; j < 32; j++) {
            const int kp = mh * 32 + j;
            float x0 = valid ? __ldcs(xr + (long)kp * 12800) : 0.f;
            float x1 = valid ? __ldcs(xr + (long)kp * 12800 + 6400) : 0.f;
            unsigned short h0 = f2h(x0), h1 = f2h(x1);
            const int si = aidx(lane, kp);
            Xhi[si] = (uint32_t)h0 | ((uint32_t)h1 << 16);
            Xlo[si] = packh(x0 - h2f(h0), x1 - h2f(h1));
        }
    }
    __syncthreads();

    const int row0 = 16 * mh;

    // ---- G = X*M (+u), 3-pass fp16 split, n-split into 2 halves (acc 32 regs) ----
    uint32_t GhA[8][4], GlA[8][4];
#pragma unroll 1
    for (int hh = 0; hh < 2; hh++) {
        float acc[8][4];
#pragma unroll
        for (int nt = 0; nt < 8; nt++)
#pragma unroll
            for (int q = 0; q < 4; q++) acc[nt][q] = 0.f;
#pragma unroll 1
        for (int pass = 0; pass < 3; pass++) {
            const uint32_t* Ai = (pass == 2) ? Xlo : Xhi;
            const uint2* Bi = WfM + ((pass == 1) ? 4096 : 0);
#pragma unroll 1
            for (int ks = 0; ks < 8; ks++) {
                const int kp0 = ks * 8 + tc;
                uint32_t a[4];
                a[0] = Ai[aidx(row0 + g, kp0)];
                a[1] = Ai[aidx(row0 + 8 + g, kp0)];
                a[2] = Ai[aidx(row0 + g, kp0 + 4)];
                a[3] = Ai[aidx(row0 + 8 + g, kp0 + 4)];
#pragma unroll
                for (int nt = 0; nt < 8; nt++) {
                    const uint2 b = __ldg(&Bi[(((hh * 8 + nt) * 8) + ks) * 32 + lane]);
                    MMA_F16(acc[nt], a, b.x, b.y);
                }
            }
        }
        // +u, convert this n-half into A-fragments (acc layout == A-frag layout)
#pragma unroll
        for (int kk2 = 0; kk2 < 4; kk2++) {
            const int kk = hh * 4 + kk2;
            float2 ua = *(const float2*)(g_u + 16 * kk + 2 * tc);
            float2 ub = *(const float2*)(g_u + 16 * kk + 8 + 2 * tc);
            float v00 = acc[2 * kk2][0] + ua.x, v01 = acc[2 * kk2][1] + ua.y;
            float v10 = acc[2 * kk2][2] + ua.x, v11 = acc[2 * kk2][3] + ua.y;
            float v20 = acc[2 * kk2 + 1][0] + ub.x, v21 = acc[2 * kk2 + 1][1] + ub.y;
            float v30 = acc[2 * kk2 + 1][2] + ub.x, v31 = acc[2 * kk2 + 1][3] + ub.y;
            unsigned short h00 = f2h(v00), h01 = f2h(v01), h10 = f2h(v10), h11 = f2h(v11);
            unsigned short h20 = f2h(v20), h21 = f2h(v21), h30 = f2h(v30), h31 = f2h(v31);
            GhA[kk][0] = (uint32_t)h00 | ((uint32_t)h01 << 16);
            GhA[kk][1] = (uint32_t)h10 | ((uint32_t)h11 << 16);
            GhA[kk][2] = (uint32_t)h20 | ((uint32_t)h21 << 16);
            GhA[kk][3] = (uint32_t)h30 | ((uint32_t)h31 << 16);
            GlA[kk][0] = packh(v00 - h2f(h00), v01 - h2f(h01));
            GlA[kk][1] = packh(v10 - h2f(h10), v11 - h2f(h11));
            GlA[kk][2] = packh(v20 - h2f(h20), v21 - h2f(h21));
            GlA[kk][3] = packh(v30 - h2f(h30), v31 - h2f(h31));
        }
    }

    // ---- S = G * X^T (3-pass), B-frags from X images ----
    float S[4][4];
#pragma unroll
    for (int nt = 0; nt < 4; nt++)
#pragma unroll
        for (int q = 0; q < 4; q++) S[nt][q] = 0.f;
#pragma unroll 1
    for (int pass = 0; pass < 3; pass++) {
        const uint32_t(*Aa)[4] = (pass == 2) ? GlA : GhA;
        const uint32_t* Bi = (pass == 1) ? Xlo : Xhi;
#pragma unroll 1
        for (int ks = 0; ks < 8; ks++) {
#pragma unroll
            for (int nt = 0; nt < 4; nt++) {
                uint32_t b0 = Bi[aidx(8 * nt + g, 8 * ks + tc)];
                uint32_t b1 = Bi[aidx(8 * nt + g, 8 * ks + tc + 4)];
                MMA_F16(S[nt], Aa[ks], b0, b1);
            }
        }
    }

    // ---- bias + mask + softmax (rows live in 4-lane groups) ----
    {
        const int v0 = row0 + g;
        const int v1c = (v0 + 8 < 25) ? v0 + 8 : 24;  // index clamp only
#pragma unroll
        for (int nt = 0; nt < 4; nt++) {
            const int w0 = 8 * nt + 2 * tc, w1 = w0 + 1;
            if (w0 < 25) {
                S[nt][0] += g_bias[v0 * 26 + w0];
                S[nt][2] += g_bias[v1c * 26 + w0];
            } else {
                S[nt][0] = -1e30f;
                S[nt][2] = -1e30f;
            }
            if (w1 < 25) {
                S[nt][1] += g_bias[v0 * 26 + w1];
                S[nt][3] += g_bias[v1c * 26 + w1];
            } else {
                S[nt][1] = -1e30f;
                S[nt][3] = -1e30f;
            }
        }
    }
#pragma unroll
    for (int h = 0; h < 2; h++) {
        float mx = -1e30f;
#pragma unroll
        for (int nt = 0; nt < 4; nt++)
            mx = fmaxf(mx, fmaxf(S[nt][2 * h], S[nt][2 * h + 1]));
        mx = fmaxf(mx, __shfl_xor_sync(0xffffffffu, mx, 1));
        mx = fmaxf(mx, __shfl_xor_sync(0xffffffffu, mx, 2));
        float sum = 0.f;
#pragma unroll
        for (int nt = 0; nt < 4; nt++) {
            float e0 = __expf(S[nt][2 * h] - mx);
            float e1 = __expf(S[nt][2 * h + 1] - mx);
            S[nt][2 * h] = e0;
            S[nt][2 * h + 1] = e1;
            sum += e0 + e1;
        }
        sum += __shfl_xor_sync(0xffffffffu, sum, 1);
        sum += __shfl_xor_sync(0xffffffffu, sum, 2);
        float inv = __fdividef(1.f, sum);
#pragma unroll
        for (int nt = 0; nt < 4; nt++) {
            S[nt][2 * h] *= inv;
            S[nt][2 * h + 1] *= inv;
        }
    }

    // ---- P -> fp16 A-fragments (in-register; S acc layout == A-frag layout) ----
    uint32_t PA[2][4];
#pragma unroll
    for (int ks = 0; ks < 2; ks++) {
        PA[ks][0] = packh(S[2 * ks][0], S[2 * ks][1]);
        PA[ks][1] = packh(S[2 * ks][2], S[2 * ks][3]);
        PA[ks][2] = packh(S[2 * ks + 1][0], S[2 * ks + 1][1]);
        PA[ks][3] = packh(S[2 * ks + 1][2], S[2 * ks + 1][3]);
    }

    // ---- V = X * wv^T, single-pass fp16 (A = Xhi, B = Vf16 via L1) ----
    float accV[16][4];
#pragma unroll
    for (int nt = 0; nt < 16; nt++)
#pragma unroll
        for (int q = 0; q < 4; q++) accV[nt][q] = 0.f;
#pragma unroll 1
    for (int ks = 0; ks < 8; ks++) {
        const int kp0 = ks * 8 + tc;
        uint32_t a[4];
        a[0] = Xhi[aidx(row0 + g, kp0)];
        a[1] = Xhi[aidx(row0 + 8 + g, kp0)];
        a[2] = Xhi[aidx(row0 + g, kp0 + 4)];
        a[3] = Xhi[aidx(row0 + 8 + g, kp0 + 4)];
#pragma unroll
        for (int nt = 0; nt < 16; nt++) {
            const uint2 b = __ldg(&WfV[(nt * 8 + ks) * 32 + lane]);
            MMA_F16(accV[nt], a, b.x, b.y);
        }
    }
    __syncthreads();  // all warps done reading X images

    // ---- Vso overlay: V^T fp16 [o][w], fp16 row stride 40 (u32 stride 20) ----
    unsigned short* Vso = (unsigned short*)Xhi;  // 2560 u32 < 4096 (tile region)
#pragma unroll
    for (int nt = 0; nt < 16; nt++) {
        const int r0 = row0 + g, o0 = 8 * nt + 2 * tc;
        Vso[o0 * 40 + r0] = f2h(accV[nt][0]);
        Vso[(o0 + 1) * 40 + r0] = f2h(accV[nt][1]);
        Vso[o0 * 40 + r0 + 8] = f2h(accV[nt][2]);
        Vso[(o0 + 1) * 40 + r0 + 8] = f2h(accV[nt][3]);
    }
    __syncthreads();

    // ---- PV: out[v][o] = P*V via MMA (k = w padded to 32; pads are exact zeros) ----
    float accO[16][4];
#pragma unroll
    for (int nt = 0; nt < 16; nt++) {
        float2 bb = *(const float2*)(bv + 8 * nt + 2 * tc);
        accO[nt][0] = bb.x;
        accO[nt][1] = bb.y;
        accO[nt][2] = bb.x;
        accO[nt][3] = bb.y;
    }
    {
        const uint32_t* VsoU = (const uint32_t*)Vso;
#pragma unroll
        for (int ks = 0; ks < 2; ks++) {
#pragma unroll
            for (int nt = 0; nt < 16; nt++) {
                const int orow = (8 * nt + g) * 20;
                uint32_t b0 = VsoU[orow + 8 * ks + tc];
                uint32_t b1 = VsoU[orow + 8 * ks + 4 + tc];
                MMA_F16(accO[nt], PA[ks], b0, b1);
            }
        }
    }
    __syncthreads();  // PV reads of Vso done before overwrite

    // ---- stage outs[o][v] (overwrite tile region), then coalesced store ----
    float* outs = (float*)Xhi;  // 128*26 floats = 3328 u32 < 4096
    {
        const int v0 = row0 + g;
        const int v1 = v0 + 8;
#pragma unroll
        for (int nt = 0; nt < 16; nt++) {
            const int o0 = 8 * nt + 2 * tc;
            outs[o0 * 26 + v0] = accO[nt][0];
            outs[(o0 + 1) * 26 + v0] = accO[nt][1];
            if (v1 < 25) {
                outs[o0 * 26 + v1] = accO[nt][2];
                outs[(o0 + 1) * 26 + v1] = accO[nt][3];
            }
        }
    }
    __syncthreads();

    const long obase = (long)n * 819200 + (long)t * 25;
#pragma unroll 4
    for (int idx = lane + 32 * mh; idx < 3200; idx += 64) {
        const int oo = idx / 25;
        const int v = idx - oo * 25;
        __stcs(&out[obase + (long)oo * 6400 + v], outs[oo * 26 + v]);
    }
}

extern "C" void kernel_launch(void* const* d_in, const int* in_sizes, int n_in,
                              void* d_out, int out_size) {
    (void)in_sizes; (void)n_in; (void)out_size;
    const float* x = (const float*)d_in[0];
    const float* wq = (const float*)d_in[1];
    const float* bq = (const float*)d_in[2];
    const float* wk = (const float*)d_in[3];
    // d_in[4] = bk: softmax-invariant (row-constant), unused
    const float* wv = (const float*)d_in[5];
    const float* bv = (const float*)d_in[6];
    const float* be = (const float*)d_in[7];
    const int* hop = (const int*)d_in[8];

    cudaFuncSetAttribute(fused_kernel, cudaFuncAttributeMaxDynamicSharedMemorySize,
                         65536);

    precompute_kernel<<<130, 128>>>(wq, bq, wk, wv, be, hop);
    fused_kernel<<<NT_TOTAL / 4, 256, 65536>>>(x, bv, (float*)d_out);
}